// round 1
// baseline (speedup 1.0000x reference)
#include <cuda_runtime.h>
#include <math.h>
#include <stdint.h>

// Problem constants (GemmaAttention: B=2, S=2048, HID=2048, H=8, KH=1, D=256)
#define BB   2
#define SSQ  2048
#define HIDD 2048
#define HH   8
#define DD   256

// SGEMM tile config
constexpr int BM = 128, BN = 128, BKK = 16, TM = 8, TN = 8;
constexpr int NTH = (BM / TM) * (BN / TN);  // 256 threads

// Scratch (static device arrays — no allocation allowed)
__device__ float g_Q[(size_t)BB * SSQ * HH * DD];     // (b, s, h, d)
__device__ float g_K[(size_t)BB * SSQ * DD];          // (b, s, d)
__device__ float g_V[(size_t)BB * SSQ * DD];          // (b, s, d)
__device__ float g_Vt[(size_t)BB * DD * SSQ];         // (b, d, s)
__device__ float g_Ctx[(size_t)BB * SSQ * HH * DD];   // (b, s, h*d)
__device__ float g_Scores[(size_t)BB * HH * SSQ * SSQ]; // fallback if attn not in d_out

// ---------------------------------------------------------------------------
// Generic NT SGEMM body: C[i,j] = alpha * sum_k A[i,k]*B[j,k] + bias[j]
// Requires: M % BM == 0, N % BN == 0, K % BKK == 0, all ld* % 4 == 0,
// 16B-aligned base pointers. brow = blockIdx.y, bcol = blockIdx.x.
// ---------------------------------------------------------------------------
__device__ __forceinline__ void gemm_nt_body(
    const float* __restrict__ A, int lda,
    const float* __restrict__ B, int ldb,
    const float* __restrict__ bias, float alpha,
    float* __restrict__ C, int ldc, int K)
{
    const int brow = blockIdx.y;
    const int bcol = blockIdx.x;

    __shared__ float As[BKK][BM + 4];
    __shared__ float Bs[BKK][BN + 4];

    const int tid = threadIdx.x;
    const int tx = tid & 15;   // 16 col-groups
    const int ty = tid >> 4;   // 16 row-groups

    float acc[TM][TN];
#pragma unroll
    for (int i = 0; i < TM; i++)
#pragma unroll
        for (int j = 0; j < TN; j++) acc[i][j] = 0.f;

    const float* Ab = A + (size_t)brow * BM * lda;
    const float* Bb = B + (size_t)bcol * BN * ldb;

    for (int kt = 0; kt < K; kt += BKK) {
        // Load 128x16 tiles of A and B (transposed into SMEM). 512 float4 each.
#pragma unroll
        for (int it = 0; it < 2; it++) {
            int idx = tid + it * NTH;
            int row = idx >> 2;
            int c4  = (idx & 3) << 2;
            float4 va = *reinterpret_cast<const float4*>(Ab + (size_t)row * lda + kt + c4);
            As[c4 + 0][row] = va.x; As[c4 + 1][row] = va.y;
            As[c4 + 2][row] = va.z; As[c4 + 3][row] = va.w;
            float4 vb = *reinterpret_cast<const float4*>(Bb + (size_t)row * ldb + kt + c4);
            Bs[c4 + 0][row] = vb.x; Bs[c4 + 1][row] = vb.y;
            Bs[c4 + 2][row] = vb.z; Bs[c4 + 3][row] = vb.w;
        }
        __syncthreads();

#pragma unroll
        for (int k = 0; k < BKK; k++) {
            float a[TM], b[TN];
#pragma unroll
            for (int i = 0; i < TM; i++) a[i] = As[k][ty * TM + i];
#pragma unroll
            for (int j = 0; j < TN; j++) b[j] = Bs[k][tx * TN + j];
#pragma unroll
            for (int i = 0; i < TM; i++)
#pragma unroll
                for (int j = 0; j < TN; j++) acc[i][j] = fmaf(a[i], b[j], acc[i][j]);
        }
        __syncthreads();
    }

#pragma unroll
    for (int i = 0; i < TM; i++) {
        size_t row = (size_t)brow * BM + ty * TM + i;
#pragma unroll
        for (int j = 0; j < TN; j += 4) {
            int col = bcol * BN + tx * TN + j;
            float4 v;
            v.x = alpha * acc[i][j + 0] + (bias ? bias[col + 0] : 0.f);
            v.y = alpha * acc[i][j + 1] + (bias ? bias[col + 1] : 0.f);
            v.z = alpha * acc[i][j + 2] + (bias ? bias[col + 2] : 0.f);
            v.w = alpha * acc[i][j + 3] + (bias ? bias[col + 3] : 0.f);
            *reinterpret_cast<float4*>(C + row * ldc + col) = v;
        }
    }
}

// ---------------------------------------------------------------------------
// Thin GEMM wrappers (device globals referenced in device code)
// ---------------------------------------------------------------------------
__global__ void __launch_bounds__(NTH) k_gemm_q(const float* hs, const float* W, const float* b) {
    gemm_nt_body(hs, HIDD, W, HIDD, b, 1.f, g_Q, HH * DD, HIDD);
}
__global__ void __launch_bounds__(NTH) k_gemm_kproj(const float* hs, const float* W, const float* b) {
    gemm_nt_body(hs, HIDD, W, HIDD, b, 1.f, g_K, DD, HIDD);
}
__global__ void __launch_bounds__(NTH) k_gemm_vproj(const float* hs, const float* W, const float* b) {
    gemm_nt_body(hs, HIDD, W, HIDD, b, 1.f, g_V, DD, HIDD);
}
// scores[b,h,n,m] = (q[b,n,h,:] . k[b,m,:]) / 16 + mask[b,m]
__global__ void __launch_bounds__(NTH) k_scores(const float* mask, float* attn) {
    int bh = blockIdx.z; int b = bh >> 3; int h = bh & 7;
    gemm_nt_body(g_Q + (size_t)b * SSQ * HH * DD + h * DD, HH * DD,
                 g_K + (size_t)b * SSQ * DD, DD,
                 mask + (size_t)b * SSQ, 0.0625f,
                 attn + (size_t)bh * SSQ * SSQ, SSQ, DD);
}
// ctx[b,n,h,d] = sum_m attn[b,h,n,m] * Vt[b,d,m]
__global__ void __launch_bounds__(NTH) k_ctx(const float* attn) {
    int bh = blockIdx.z; int b = bh >> 3; int h = bh & 7;
    gemm_nt_body(attn + (size_t)bh * SSQ * SSQ, SSQ,
                 g_Vt + (size_t)b * DD * SSQ, SSQ,
                 nullptr, 1.f,
                 g_Ctx + (size_t)b * SSQ * HH * DD + h * DD, HH * DD, SSQ);
}
__global__ void __launch_bounds__(NTH) k_gemm_out(const float* Wo, const float* bo, float* out) {
    gemm_nt_body(g_Ctx, HH * DD, Wo, HIDD, bo, 1.f, out, HIDD, HH * DD);
}

// ---------------------------------------------------------------------------
// RoPE on Q (8 heads) and K (1 head) in place. One block per (b,s), 128 threads.
// ---------------------------------------------------------------------------
__global__ void k_rope(const int* __restrict__ pos_ids) {
    int bs = blockIdx.x;
    int i  = threadIdx.x;  // 0..127 (half-dim index)
    // inv_freq = 10000^(-i/128), computed in double for phase accuracy
    double invf = exp(-(double)i * (9.210340371976182736 / 128.0)); // ln(10000)
    double f = (double)pos_ids[bs] * invf;
    float c = (float)cos(f);
    float s = (float)sin(f);

    float* kr = g_K + (size_t)bs * DD;
    float x1 = kr[i], x2 = kr[i + 128];
    kr[i]       = c * x1 - s * x2;
    kr[i + 128] = s * x1 + c * x2;

    float* qr = g_Q + (size_t)bs * HH * DD;
#pragma unroll
    for (int h = 0; h < HH; h++) {
        float y1 = qr[h * DD + i], y2 = qr[h * DD + i + 128];
        qr[h * DD + i]       = c * y1 - s * y2;
        qr[h * DD + i + 128] = s * y1 + c * y2;
    }
}

// ---------------------------------------------------------------------------
// Transpose V: (b, m, d) -> (b, d, m)
// ---------------------------------------------------------------------------
__global__ void k_transpose_v() {
    __shared__ float tile[32][33];
    int b  = blockIdx.z;
    int m0 = blockIdx.y * 32;
    int d0 = blockIdx.x * 32;
    int x = threadIdx.x, y = threadIdx.y;  // (32, 8)
#pragma unroll
    for (int j = 0; j < 32; j += 8)
        tile[y + j][x] = g_V[((size_t)(b * SSQ + m0 + y + j)) * DD + d0 + x];
    __syncthreads();
#pragma unroll
    for (int j = 0; j < 32; j += 8)
        g_Vt[(size_t)b * DD * SSQ + (size_t)(d0 + y + j) * SSQ + m0 + x] = tile[x][y + j];
}

// ---------------------------------------------------------------------------
// Row softmax over 2048, in place. One block per row (B*H*S rows), 256 threads.
// ---------------------------------------------------------------------------
__global__ void k_softmax(float* __restrict__ attn) {
    size_t row = blockIdx.x;
    float* p = attn + row * SSQ;
    int tid = threadIdx.x;

    float v[8];
    float m = -1e30f;
#pragma unroll
    for (int i = 0; i < 8; i++) { v[i] = p[i * 256 + tid]; m = fmaxf(m, v[i]); }

    __shared__ float red[256];
    red[tid] = m; __syncthreads();
    for (int s = 128; s > 0; s >>= 1) {
        if (tid < s) red[tid] = fmaxf(red[tid], red[tid + s]);
        __syncthreads();
    }
    m = red[0]; __syncthreads();

    float sum = 0.f;
#pragma unroll
    for (int i = 0; i < 8; i++) { v[i] = __expf(v[i] - m); sum += v[i]; }
    red[tid] = sum; __syncthreads();
    for (int s = 128; s > 0; s >>= 1) {
        if (tid < s) red[tid] += red[tid + s];
        __syncthreads();
    }
    float inv = 1.f / red[0];
#pragma unroll
    for (int i = 0; i < 8; i++) p[i * 256 + tid] = v[i] * inv;
}

// ---------------------------------------------------------------------------
// Launch: QKV proj -> RoPE -> V transpose -> scores(+mask,scale) -> softmax
//         -> attn@V -> out proj. Output = [out (B,S,HID) | attn (B,H,S,S)].
// ---------------------------------------------------------------------------
extern "C" void kernel_launch(void* const* d_in, const int* in_sizes, int n_in,
                              void* d_out, int out_size) {
    const float* hs   = (const float*)d_in[0];
    const float* mask = (const float*)d_in[1];
    const int*   pos  = (const int*)d_in[2];
    const float* Wq   = (const float*)d_in[3];
    const float* bq   = (const float*)d_in[4];
    const float* Wk   = (const float*)d_in[5];
    const float* bk   = (const float*)d_in[6];
    const float* Wv   = (const float*)d_in[7];
    const float* bv   = (const float*)d_in[8];
    const float* Wo   = (const float*)d_in[9];
    const float* bo   = (const float*)d_in[10];
    float* out = (float*)d_out;

    const size_t out_elems  = (size_t)BB * SSQ * HIDD;
    const size_t attn_elems = (size_t)BB * HH * SSQ * SSQ;

    float* attn;
    if ((size_t)out_size >= out_elems + attn_elems) {
        attn = out + out_elems;  // tuple output: (out, attn)
    } else {
        void* p = nullptr;
        cudaGetSymbolAddress(&p, g_Scores);  // pure lookup, capture-safe
        attn = (float*)p;
    }

    dim3 blk(NTH);
    k_gemm_q    <<<dim3(HIDD / BN, (BB * SSQ) / BM), blk>>>(hs, Wq, bq);
    k_gemm_kproj<<<dim3(DD   / BN, (BB * SSQ) / BM), blk>>>(hs, Wk, bk);
    k_gemm_vproj<<<dim3(DD   / BN, (BB * SSQ) / BM), blk>>>(hs, Wv, bv);
    k_rope      <<<BB * SSQ, 128>>>(pos);
    k_transpose_v<<<dim3(DD / 32, SSQ / 32, BB), dim3(32, 8)>>>();
    k_scores    <<<dim3(SSQ / BN, SSQ / BM, BB * HH), blk>>>(mask, attn);
    k_softmax   <<<BB * HH * SSQ, 256>>>(attn);
    k_ctx       <<<dim3(DD / BN, SSQ / BM, BB * HH), blk>>>(attn);
    k_gemm_out  <<<dim3(HIDD / BN, (BB * SSQ) / BM), blk>>>(Wo, bo, out);
}

// round 4
// speedup vs baseline: 1.9692x; 1.9692x over previous
#include <cuda_runtime.h>
#include <cuda_bf16.h>
#include <math.h>
#include <stdint.h>

// Problem constants (GemmaAttention: B=2, S=2048, HID=2048, H=8, KH=1, D=256)
#define BB   2
#define SSQ  2048
#define HIDD 2048
#define HH   8
#define DD   256

typedef __nv_bfloat16 bf16;
typedef long long ll;

// ---------------------------------------------------------------------------
// Portable (sm_80+) tensor-core helpers: mma.sync + ldmatrix + cp.async
// ---------------------------------------------------------------------------
__device__ __forceinline__ uint32_t smem_u32(const void* p) {
    uint32_t a;
    asm("{ .reg .u64 t; cvta.to.shared.u64 t, %1; cvt.u32.u64 %0, t; }" : "=r"(a) : "l"(p));
    return a;
}
__device__ __forceinline__ void cp16(uint32_t s, const void* g) {
    asm volatile("cp.async.cg.shared.global [%0], [%1], 16;" :: "r"(s), "l"(g));
}
#define CP_COMMIT() asm volatile("cp.async.commit_group;" ::: "memory")
#define CP_WAIT(n)  asm volatile("cp.async.wait_group %0;" :: "n"(n) : "memory")
#define LDMX4(r, a) \
    asm volatile("ldmatrix.sync.aligned.m8n8.x4.shared.b16 {%0,%1,%2,%3}, [%4];" \
        : "=r"((r)[0]), "=r"((r)[1]), "=r"((r)[2]), "=r"((r)[3]) : "r"(a))

__device__ __forceinline__ void mma16816(float* c, const uint32_t* a,
                                         uint32_t b0, uint32_t b1) {
    asm volatile(
        "mma.sync.aligned.m16n8k16.row.col.f32.bf16.bf16.f32 "
        "{%0,%1,%2,%3}, {%4,%5,%6,%7}, {%8,%9}, {%0,%1,%2,%3};"
        : "+f"(c[0]), "+f"(c[1]), "+f"(c[2]), "+f"(c[3])
        : "r"(a[0]), "r"(a[1]), "r"(a[2]), "r"(a[3]), "r"(b0), "r"(b1));
}

// ---------------------------------------------------------------------------
// Scratch (static device arrays — no allocation allowed)
// Split-bf16 layout: A-style row = [hi | hi | lo] (3K), B-style = [hi | lo | hi]
// ---------------------------------------------------------------------------
__device__ bf16  g_hsb [(size_t)BB * SSQ * 3 * HIDD];
__device__ bf16  g_Wqb [(size_t)HH * DD * 3 * HIDD];
__device__ bf16  g_Wkb [(size_t)DD * 3 * HIDD];
__device__ bf16  g_Wvb [(size_t)DD * 3 * HIDD];
__device__ bf16  g_Wob [(size_t)HIDD * 3 * HH * DD];
__device__ float g_Q   [(size_t)BB * SSQ * HH * DD];
__device__ float g_K   [(size_t)BB * SSQ * DD];
__device__ float g_V   [(size_t)BB * SSQ * DD];
__device__ float g_Vt  [(size_t)BB * DD * SSQ];
__device__ bf16  g_Qb  [(size_t)BB * SSQ * HH * 3 * DD];
__device__ bf16  g_Kb  [(size_t)BB * SSQ * 3 * DD];
__device__ bf16  g_Vtb [(size_t)BB * DD * 3 * SSQ];
__device__ bf16  g_attnb[(size_t)BB * HH * SSQ * 3 * SSQ];
__device__ float g_Ctx [(size_t)BB * SSQ * HH * DD];
__device__ bf16  g_Ctxb[(size_t)BB * SSQ * 3 * HH * DD];
__device__ float g_Scores[(size_t)BB * HH * SSQ * SSQ];  // fallback if attn not in d_out

// ---------------------------------------------------------------------------
// Split converter: fp32 (rows x K) -> bf16 (rows x 3K).
// amode=1: [hi,hi,lo] (A operand), amode=0: [hi,lo,hi] (B operand). K = 1<<ks.
// ---------------------------------------------------------------------------
__global__ void k_cvt_split(const float* __restrict__ in, bf16* __restrict__ outp,
                            int ks, int amode, ll n2) {
    ll i = (ll)blockIdx.x * blockDim.x + threadIdx.x;
    if (i >= n2) return;
    ll e = i * 2;
    ll Kd = 1LL << ks;
    ll row = e >> ks;
    int k = (int)(e & (Kd - 1));
    float2 x = *reinterpret_cast<const float2*>(in + e);
    bf16 h0 = __float2bfloat16(x.x), h1 = __float2bfloat16(x.y);
    bf16 l0 = __float2bfloat16(x.x - __bfloat162float(h0));
    bf16 l1 = __float2bfloat16(x.y - __bfloat162float(h1));
    __nv_bfloat162 hi; hi.x = h0; hi.y = h1;
    __nv_bfloat162 lo; lo.x = l0; lo.y = l1;
    bf16* ob = outp + row * (3 * Kd) + k;
    *reinterpret_cast<__nv_bfloat162*>(ob)          = hi;
    *reinterpret_cast<__nv_bfloat162*>(ob + Kd)     = amode ? hi : lo;
    *reinterpret_cast<__nv_bfloat162*>(ob + 2 * Kd) = amode ? lo : hi;
}

// ---------------------------------------------------------------------------
// mma.sync bf16 GEMM: C[i,j] = alpha * sum_k A[i,k]*B[j,k] + bias[j]
// CTA tile 128x128, 8 warps (2M x 4N, warp tile 64x32), K-chunk 32,
// cp.async double-buffered SMEM (rows padded to 40 bf16 = 80B: ldmatrix
// conflict-free). blockIdx.z -> (b = z>>3, h = z&7) batched strides.
// ---------------------------------------------------------------------------
__global__ void __launch_bounds__(256, 2) k_mma_gemm(
    const bf16* __restrict__ A, ll lda, ll sAb, ll sAh,
    const bf16* __restrict__ Bm, ll ldb, ll sBb, ll sBh,
    const float* __restrict__ bias, ll sbb, float alpha,
    float* __restrict__ C, ll ldc, ll sCb, ll sCh, int K)
{
    __shared__ bf16 sA[2][128][40];
    __shared__ bf16 sB[2][128][40];

    const int tid = threadIdx.x, lane = tid & 31, wid = tid >> 5;
    const int wm = wid & 1, wn = wid >> 1;           // 2 x 4 warp grid
    const int z = blockIdx.z, b = z >> 3, h = z & 7;
    const bf16* Ab = A + b * sAb + h * sAh + (ll)blockIdx.y * 128 * lda;
    const bf16* Bb = Bm + b * sBb + h * sBh + (ll)blockIdx.x * 128 * ldb;

    float acc[4][4][4];
#pragma unroll
    for (int i = 0; i < 4; i++)
#pragma unroll
        for (int j = 0; j < 4; j++)
#pragma unroll
            for (int r = 0; r < 4; r++) acc[i][j][r] = 0.f;

    // per-thread ldmatrix source coordinates
    const int aRow = wm * 64 + (lane & 15);
    const int aCol = (lane >> 4) * 8;
    const int bRow = wn * 32 + (lane >> 4) * 8 + (lane & 7);
    const int bCol = ((lane >> 3) & 1) * 8;

    const int nch = K >> 5;

    // stage loader: 512 16B vectors each for A and B, 256 threads x 2
#define LOAD_STAGE(st, kt)                                                     \
    do {                                                                       \
        _Pragma("unroll")                                                      \
        for (int it = 0; it < 2; it++) {                                       \
            int idx = tid + it * 256;                                          \
            int r = idx >> 2, cc = (idx & 3) * 8;                              \
            cp16(smem_u32(&sA[st][r][cc]), Ab + (ll)r * lda + (kt) + cc);      \
            cp16(smem_u32(&sB[st][r][cc]), Bb + (ll)r * ldb + (kt) + cc);      \
        }                                                                      \
        CP_COMMIT();                                                           \
    } while (0)

    LOAD_STAGE(0, 0);

    for (int c = 0; c < nch; c++) {
        if (c + 1 < nch) {
            LOAD_STAGE((c + 1) & 1, (c + 1) * 32);
            CP_WAIT(1);
        } else {
            CP_WAIT(0);
        }
        __syncthreads();

        const int st = c & 1;
        const uint32_t aBase = smem_u32(&sA[st][0][0]);
        const uint32_t bBase = smem_u32(&sB[st][0][0]);
#pragma unroll
        for (int k0 = 0; k0 < 32; k0 += 16) {
            uint32_t af[4][4], bfm[2][4];
#pragma unroll
            for (int i = 0; i < 4; i++) {
                uint32_t ad = aBase + (uint32_t)(((aRow + i * 16) * 40 + k0 + aCol) * 2);
                LDMX4(af[i], ad);
            }
#pragma unroll
            for (int j2 = 0; j2 < 2; j2++) {
                uint32_t bd = bBase + (uint32_t)(((bRow + j2 * 16) * 40 + k0 + bCol) * 2);
                LDMX4(bfm[j2], bd);
            }
#pragma unroll
            for (int i = 0; i < 4; i++)
#pragma unroll
                for (int j = 0; j < 4; j++)
                    mma16816(acc[i][j], af[i],
                             bfm[j >> 1][(j & 1) * 2], bfm[j >> 1][(j & 1) * 2 + 1]);
        }
        __syncthreads();
    }
#undef LOAD_STAGE

    // Epilogue: alpha * acc + bias[col]
    const int g = lane >> 2, t = lane & 3;
    float* Cp = C + b * sCb + h * sCh;
    const float* bp = bias ? bias + b * sbb + (ll)blockIdx.x * 128 : nullptr;
#pragma unroll
    for (int i = 0; i < 4; i++) {
        ll r0 = (ll)blockIdx.y * 128 + wm * 64 + i * 16 + g;
#pragma unroll
        for (int j = 0; j < 4; j++) {
            int lcol = wn * 32 + j * 8 + t * 2;
            ll col = (ll)blockIdx.x * 128 + lcol;
            float b0 = bp ? bp[lcol] : 0.f;
            float b1 = bp ? bp[lcol + 1] : 0.f;
            float2 v0, v1;
            v0.x = alpha * acc[i][j][0] + b0;
            v0.y = alpha * acc[i][j][1] + b1;
            v1.x = alpha * acc[i][j][2] + b0;
            v1.y = alpha * acc[i][j][3] + b1;
            *reinterpret_cast<float2*>(Cp + r0 * ldc + col)       = v0;
            *reinterpret_cast<float2*>(Cp + (r0 + 8) * ldc + col) = v1;
        }
    }
}

// ---------------------------------------------------------------------------
// RoPE on Q (8 heads) and K (1 head) in place. One block per (b,s), 128 threads.
// ---------------------------------------------------------------------------
__global__ void k_rope(const int* __restrict__ pos_ids) {
    int bs = blockIdx.x;
    int i  = threadIdx.x;
    double invf = exp(-(double)i * (9.210340371976182736 / 128.0));
    double f = (double)pos_ids[bs] * invf;
    float c = (float)cos(f);
    float s = (float)sin(f);

    float* kr = g_K + (size_t)bs * DD;
    float x1 = kr[i], x2 = kr[i + 128];
    kr[i]       = c * x1 - s * x2;
    kr[i + 128] = s * x1 + c * x2;

    float* qr = g_Q + (size_t)bs * HH * DD;
#pragma unroll
    for (int h = 0; h < HH; h++) {
        float y1 = qr[h * DD + i], y2 = qr[h * DD + i + 128];
        qr[h * DD + i]       = c * y1 - s * y2;
        qr[h * DD + i + 128] = s * y1 + c * y2;
    }
}

// ---------------------------------------------------------------------------
// Transpose V: (b, m, d) -> (b, d, m)
// ---------------------------------------------------------------------------
__global__ void k_transpose_v() {
    __shared__ float tile[32][33];
    int b  = blockIdx.z;
    int m0 = blockIdx.y * 32;
    int d0 = blockIdx.x * 32;
    int x = threadIdx.x, y = threadIdx.y;
#pragma unroll
    for (int j = 0; j < 32; j += 8)
        tile[y + j][x] = g_V[((size_t)(b * SSQ + m0 + y + j)) * DD + d0 + x];
    __syncthreads();
#pragma unroll
    for (int j = 0; j < 32; j += 8)
        g_Vt[(size_t)b * DD * SSQ + (size_t)(d0 + y + j) * SSQ + m0 + x] = tile[x][y + j];
}

// ---------------------------------------------------------------------------
// Row softmax over 2048, in place.
// ---------------------------------------------------------------------------
__global__ void k_softmax(float* __restrict__ attn) {
    size_t row = blockIdx.x;
    float* p = attn + row * SSQ;
    int tid = threadIdx.x;

    float v[8];
    float m = -1e30f;
#pragma unroll
    for (int i = 0; i < 8; i++) { v[i] = p[i * 256 + tid]; m = fmaxf(m, v[i]); }

    __shared__ float red[256];
    red[tid] = m; __syncthreads();
    for (int s = 128; s > 0; s >>= 1) {
        if (tid < s) red[tid] = fmaxf(red[tid], red[tid + s]);
        __syncthreads();
    }
    m = red[0]; __syncthreads();

    float sum = 0.f;
#pragma unroll
    for (int i = 0; i < 8; i++) { v[i] = __expf(v[i] - m); sum += v[i]; }
    red[tid] = sum; __syncthreads();
    for (int s = 128; s > 0; s >>= 1) {
        if (tid < s) red[tid] += red[tid + s];
        __syncthreads();
    }
    float inv = 1.f / red[0];
#pragma unroll
    for (int i = 0; i < 8; i++) p[i * 256 + tid] = v[i] * inv;
}

// ---------------------------------------------------------------------------
// Launch
// ---------------------------------------------------------------------------
extern "C" void kernel_launch(void* const* d_in, const int* in_sizes, int n_in,
                              void* d_out, int out_size) {
    const float* hs   = (const float*)d_in[0];
    const float* mask = (const float*)d_in[1];
    const int*   pos  = (const int*)d_in[2];
    const float* Wq   = (const float*)d_in[3];
    const float* bq   = (const float*)d_in[4];
    const float* Wk   = (const float*)d_in[5];
    const float* bk   = (const float*)d_in[6];
    const float* Wv   = (const float*)d_in[7];
    const float* bv   = (const float*)d_in[8];
    const float* Wo   = (const float*)d_in[9];
    const float* bo   = (const float*)d_in[10];
    float* out = (float*)d_out;

    const size_t out_elems  = (size_t)BB * SSQ * HIDD;
    const size_t attn_elems = (size_t)BB * HH * SSQ * SSQ;

    float* attn;
    if ((size_t)out_size >= out_elems + attn_elems) {
        attn = out + out_elems;
    } else {
        void* p = nullptr;
        cudaGetSymbolAddress(&p, g_Scores);
        attn = (float*)p;
    }

    // Resolve scratch symbol addresses (host side, capture-safe lookups)
    bf16 *hsb, *Wqb, *Wkb, *Wvb, *Wob, *Qb, *Kb, *Vtb, *attnb, *Ctxb;
    float *Qf, *Kf, *Vf, *Vtf, *Ctxf;
    { void* p;
      cudaGetSymbolAddress(&p, g_hsb);  hsb  = (bf16*)p;
      cudaGetSymbolAddress(&p, g_Wqb);  Wqb  = (bf16*)p;
      cudaGetSymbolAddress(&p, g_Wkb);  Wkb  = (bf16*)p;
      cudaGetSymbolAddress(&p, g_Wvb);  Wvb  = (bf16*)p;
      cudaGetSymbolAddress(&p, g_Wob);  Wob  = (bf16*)p;
      cudaGetSymbolAddress(&p, g_Qb);   Qb   = (bf16*)p;
      cudaGetSymbolAddress(&p, g_Kb);   Kb   = (bf16*)p;
      cudaGetSymbolAddress(&p, g_Vtb);  Vtb  = (bf16*)p;
      cudaGetSymbolAddress(&p, g_attnb); attnb = (bf16*)p;
      cudaGetSymbolAddress(&p, g_Ctxb); Ctxb = (bf16*)p;
      cudaGetSymbolAddress(&p, g_Q);    Qf   = (float*)p;
      cudaGetSymbolAddress(&p, g_K);    Kf   = (float*)p;
      cudaGetSymbolAddress(&p, g_V);    Vf   = (float*)p;
      cudaGetSymbolAddress(&p, g_Vt);   Vtf  = (float*)p;
      cudaGetSymbolAddress(&p, g_Ctx);  Ctxf = (float*)p;
    }

    const int T = 256;
    auto blocks = [](ll n2) { return (unsigned)((n2 + 255) / 256); };

    // 1) Split-convert hs and weights
    ll n2_hs = (ll)BB * SSQ * HIDD / 2;
    k_cvt_split<<<blocks(n2_hs), T>>>(hs, hsb, 11, 1, n2_hs);
    ll n2_wq = (ll)HH * DD * HIDD / 2;
    k_cvt_split<<<blocks(n2_wq), T>>>(Wq, Wqb, 11, 0, n2_wq);
    ll n2_wk = (ll)DD * HIDD / 2;
    k_cvt_split<<<blocks(n2_wk), T>>>(Wk, Wkb, 11, 0, n2_wk);
    k_cvt_split<<<blocks(n2_wk), T>>>(Wv, Wvb, 11, 0, n2_wk);
    ll n2_wo = (ll)HIDD * HH * DD / 2;
    k_cvt_split<<<blocks(n2_wo), T>>>(Wo, Wob, 11, 0, n2_wo);

    // 2) QKV projections (K' = 3*2048 = 6144)
    k_mma_gemm<<<dim3(16, 32, 1), T>>>(hsb, 6144, 0, 0, Wqb, 6144, 0, 0,
                                       bq, 0, 1.f, Qf, 2048, 0, 0, 6144);
    k_mma_gemm<<<dim3(2, 32, 1), T>>>(hsb, 6144, 0, 0, Wkb, 6144, 0, 0,
                                      bk, 0, 1.f, Kf, 256, 0, 0, 6144);
    k_mma_gemm<<<dim3(2, 32, 1), T>>>(hsb, 6144, 0, 0, Wvb, 6144, 0, 0,
                                      bv, 0, 1.f, Vf, 256, 0, 0, 6144);

    // 3) RoPE + V transpose
    k_rope<<<BB * SSQ, 128>>>(pos);
    k_transpose_v<<<dim3(DD / 32, SSQ / 32, BB), dim3(32, 8)>>>();

    // 4) Split-convert Q, K, Vt
    ll n2_q = (ll)BB * SSQ * HH * DD / 2;
    k_cvt_split<<<blocks(n2_q), T>>>(Qf, Qb, 8, 1, n2_q);
    ll n2_k = (ll)BB * SSQ * DD / 2;
    k_cvt_split<<<blocks(n2_k), T>>>(Kf, Kb, 8, 0, n2_k);
    ll n2_vt = (ll)BB * DD * SSQ / 2;
    k_cvt_split<<<blocks(n2_vt), T>>>(Vtf, Vtb, 11, 0, n2_vt);

    // 5) scores[b,h] = Q[b,:,h,:] K[b]^T / 16 + mask[b]   (K' = 768)
    k_mma_gemm<<<dim3(16, 16, BB * HH), T>>>(
        Qb, (ll)HH * 3 * DD, (ll)SSQ * HH * 3 * DD, 3 * DD,
        Kb, 3 * DD, (ll)SSQ * 3 * DD, 0,
        mask, SSQ, 0.0625f,
        attn, SSQ, (ll)HH * SSQ * SSQ, (ll)SSQ * SSQ, 3 * DD);

    // 6) softmax
    k_softmax<<<BB * HH * SSQ, 256>>>(attn);

    // 7) split-convert attn, ctx GEMM (K' = 6144)
    ll n2_at = (ll)BB * HH * SSQ * SSQ / 2;
    k_cvt_split<<<blocks(n2_at), T>>>(attn, attnb, 11, 1, n2_at);
    k_mma_gemm<<<dim3(2, 16, BB * HH), T>>>(
        attnb, 3 * SSQ, (ll)HH * SSQ * 3 * SSQ, (ll)SSQ * 3 * SSQ,
        Vtb, 3 * SSQ, (ll)DD * 3 * SSQ, 0,
        nullptr, 0, 1.f,
        Ctxf, HH * DD, (ll)SSQ * HH * DD, DD, 3 * SSQ);

    // 8) out projection
    ll n2_ctx = (ll)BB * SSQ * HH * DD / 2;
    k_cvt_split<<<blocks(n2_ctx), T>>>(Ctxf, Ctxb, 11, 1, n2_ctx);
    k_mma_gemm<<<dim3(16, 32, 1), T>>>(Ctxb, 6144, 0, 0, Wob, 6144, 0, 0,
                                       bo, 0, 1.f, out, 2048, 0, 0, 6144);
}

// round 7
// speedup vs baseline: 2.5544x; 1.2972x over previous
#include <cuda_runtime.h>
#include <cuda_bf16.h>
#include <math.h>
#include <stdint.h>

// Problem constants (GemmaAttention: B=2, S=2048, HID=2048, H=8, KH=1, D=256)
#define BB   2
#define SSQ  2048
#define HIDD 2048
#define HH   8
#define DD   256

typedef __nv_bfloat16 bf16;
typedef long long ll;

// ---------------------------------------------------------------------------
// Tensor-core helpers (sm_80+ portable): mma.sync + ldmatrix + cp.async
// ---------------------------------------------------------------------------
__device__ __forceinline__ uint32_t smem_u32(const void* p) {
    uint32_t a;
    asm("{ .reg .u64 t; cvta.to.shared.u64 t, %1; cvt.u32.u64 %0, t; }" : "=r"(a) : "l"(p));
    return a;
}
__device__ __forceinline__ void cp16(uint32_t s, const void* g) {
    asm volatile("cp.async.cg.shared.global [%0], [%1], 16;" :: "r"(s), "l"(g));
}
#define CP_COMMIT() asm volatile("cp.async.commit_group;" ::: "memory")
#define CP_WAIT(n)  asm volatile("cp.async.wait_group %0;" :: "n"(n) : "memory")
#define LDMX4(r, a) \
    asm volatile("ldmatrix.sync.aligned.m8n8.x4.shared.b16 {%0,%1,%2,%3}, [%4];" \
        : "=r"((r)[0]), "=r"((r)[1]), "=r"((r)[2]), "=r"((r)[3]) : "r"(a))

__device__ __forceinline__ void mma16816(float* c, const uint32_t* a,
                                         uint32_t b0, uint32_t b1) {
    asm volatile(
        "mma.sync.aligned.m16n8k16.row.col.f32.bf16.bf16.f32 "
        "{%0,%1,%2,%3}, {%4,%5,%6,%7}, {%8,%9}, {%0,%1,%2,%3};"
        : "+f"(c[0]), "+f"(c[1]), "+f"(c[2]), "+f"(c[3])
        : "r"(a[0]), "r"(a[1]), "r"(a[2]), "r"(a[3]), "r"(b0), "r"(b1));
}
__device__ __forceinline__ void mma1688(float* c, const uint32_t* a,
                                        uint32_t b0, uint32_t b1) {
    asm volatile(
        "mma.sync.aligned.m16n8k8.row.col.f32.tf32.tf32.f32 "
        "{%0,%1,%2,%3}, {%4,%5,%6,%7}, {%8,%9}, {%0,%1,%2,%3};"
        : "+f"(c[0]), "+f"(c[1]), "+f"(c[2]), "+f"(c[3])
        : "r"(a[0]), "r"(a[1]), "r"(a[2]), "r"(a[3]), "r"(b0), "r"(b1));
}
__device__ __forceinline__ uint32_t to_tf32(float x) {
    uint32_t r;
    asm("cvt.rna.tf32.f32 %0, %1;" : "=r"(r) : "f"(x));
    return r;
}

// ---------------------------------------------------------------------------
// Scratch (static device arrays — no allocation allowed)
// Split-bf16: A-style row = [hi | hi | lo] (3K), B-style = [hi | lo | hi]
// ---------------------------------------------------------------------------
__device__ bf16  g_hsb  [(size_t)BB * SSQ * 3 * HIDD];
__device__ bf16  g_Wqb  [(size_t)HH * DD * 3 * HIDD];
__device__ bf16  g_Wkvb [(size_t)2 * DD * 3 * HIDD];    // [Wk rows | Wv rows]
__device__ float g_bkv  [2 * DD];
__device__ float g_Q    [(size_t)BB * SSQ * HH * DD];   // pre-rope Q (fp32)
__device__ float g_KV   [(size_t)BB * SSQ * 2 * DD];    // [k | v] per (b,s)
__device__ bf16  g_Qb   [(size_t)BB * SSQ * HH * 3 * DD]; // rope'd, split (A-mode)
__device__ bf16  g_Kb   [(size_t)BB * SSQ * 3 * DD];      // rope'd, split (B-mode)
__device__ float g_Vt   [(size_t)BB * DD * SSQ];          // (b, d, m) fp32
__device__ float g_Ctx  [(size_t)BB * SSQ * HH * DD];
__device__ float g_Scores[(size_t)BB * HH * SSQ * SSQ];   // fallback attn buffer

// ---------------------------------------------------------------------------
// Split converter: fp32 (rows x K) -> bf16 (rows x 3K). K = 1<<ks.
// amode=1: [hi,hi,lo], amode=0: [hi,lo,hi].
// ---------------------------------------------------------------------------
__global__ void k_cvt_split(const float* __restrict__ in, bf16* __restrict__ outp,
                            int ks, int amode, ll n2) {
    ll i = (ll)blockIdx.x * blockDim.x + threadIdx.x;
    if (i >= n2) return;
    ll e = i * 2;
    ll Kd = 1LL << ks;
    ll row = e >> ks;
    int k = (int)(e & (Kd - 1));
    float2 x = *reinterpret_cast<const float2*>(in + e);
    bf16 h0 = __float2bfloat16(x.x), h1 = __float2bfloat16(x.y);
    bf16 l0 = __float2bfloat16(x.x - __bfloat162float(h0));
    bf16 l1 = __float2bfloat16(x.y - __bfloat162float(h1));
    __nv_bfloat162 hi; hi.x = h0; hi.y = h1;
    __nv_bfloat162 lo; lo.x = l0; lo.y = l1;
    bf16* ob = outp + row * (3 * Kd) + k;
    *reinterpret_cast<__nv_bfloat162*>(ob)          = hi;
    *reinterpret_cast<__nv_bfloat162*>(ob + Kd)     = amode ? hi : lo;
    *reinterpret_cast<__nv_bfloat162*>(ob + 2 * Kd) = amode ? lo : hi;
}

__global__ void k_merge_bias(const float* __restrict__ bk, const float* __restrict__ bv) {
    int t = threadIdx.x;
    g_bkv[t] = (t < DD) ? bk[t] : bv[t - DD];
}

// ---------------------------------------------------------------------------
// bf16 mma.sync GEMM: C[i,j] = alpha * sum_k A[i,k]*B[j,k] + bias[j]
// CTA 128x128, 8 warps (2x4, warp 64x32), K-chunk 32, double-buffered cp.async,
// SMEM rows padded to 40 bf16 (conflict-free ldmatrix). z -> (b=z>>3, h=z&7).
// ---------------------------------------------------------------------------
__global__ void __launch_bounds__(256, 2) k_mma_gemm(
    const bf16* __restrict__ A, ll lda, ll sAb, ll sAh,
    const bf16* __restrict__ Bm, ll ldb, ll sBb, ll sBh,
    const float* __restrict__ bias, ll sbb, float alpha,
    float* __restrict__ C, ll ldc, ll sCb, ll sCh, int K)
{
    __shared__ bf16 sA[2][128][40];
    __shared__ bf16 sB[2][128][40];

    const int tid = threadIdx.x, lane = tid & 31, wid = tid >> 5;
    const int wm = wid & 1, wn = wid >> 1;
    const int z = blockIdx.z, b = z >> 3, h = z & 7;
    const bf16* Ab = A + b * sAb + h * sAh + (ll)blockIdx.y * 128 * lda;
    const bf16* Bb = Bm + b * sBb + h * sBh + (ll)blockIdx.x * 128 * ldb;

    float acc[4][4][4];
#pragma unroll
    for (int i = 0; i < 4; i++)
#pragma unroll
        for (int j = 0; j < 4; j++)
#pragma unroll
            for (int r = 0; r < 4; r++) acc[i][j][r] = 0.f;

    const int aRow = wm * 64 + (lane & 15);
    const int aCol = (lane >> 4) * 8;
    const int bRow = wn * 32 + (lane >> 4) * 8 + (lane & 7);
    const int bCol = ((lane >> 3) & 1) * 8;

    const int nch = K >> 5;

#define LOAD_STAGE(st, kt)                                                     \
    do {                                                                       \
        _Pragma("unroll")                                                      \
        for (int it = 0; it < 2; it++) {                                       \
            int idx = tid + it * 256;                                          \
            int r = idx >> 2, cc = (idx & 3) * 8;                              \
            cp16(smem_u32(&sA[st][r][cc]), Ab + (ll)r * lda + (kt) + cc);      \
            cp16(smem_u32(&sB[st][r][cc]), Bb + (ll)r * ldb + (kt) + cc);      \
        }                                                                      \
        CP_COMMIT();                                                           \
    } while (0)

    LOAD_STAGE(0, 0);

    for (int c = 0; c < nch; c++) {
        if (c + 1 < nch) {
            LOAD_STAGE((c + 1) & 1, (c + 1) * 32);
            CP_WAIT(1);
        } else {
            CP_WAIT(0);
        }
        __syncthreads();

        const int st = c & 1;
        const uint32_t aBase = smem_u32(&sA[st][0][0]);
        const uint32_t bBase = smem_u32(&sB[st][0][0]);
#pragma unroll
        for (int k0 = 0; k0 < 32; k0 += 16) {
            uint32_t af[4][4], bfm[2][4];
#pragma unroll
            for (int i = 0; i < 4; i++) {
                uint32_t ad = aBase + (uint32_t)(((aRow + i * 16) * 40 + k0 + aCol) * 2);
                LDMX4(af[i], ad);
            }
#pragma unroll
            for (int j2 = 0; j2 < 2; j2++) {
                uint32_t bd = bBase + (uint32_t)(((bRow + j2 * 16) * 40 + k0 + bCol) * 2);
                LDMX4(bfm[j2], bd);
            }
#pragma unroll
            for (int i = 0; i < 4; i++)
#pragma unroll
                for (int j = 0; j < 4; j++)
                    mma16816(acc[i][j], af[i],
                             bfm[j >> 1][(j & 1) * 2], bfm[j >> 1][(j & 1) * 2 + 1]);
        }
        __syncthreads();
    }
#undef LOAD_STAGE

    const int g = lane >> 2, t = lane & 3;
    float* Cp = C + b * sCb + h * sCh;
    const float* bp = bias ? bias + b * sbb + (ll)blockIdx.x * 128 : nullptr;
#pragma unroll
    for (int i = 0; i < 4; i++) {
        ll r0 = (ll)blockIdx.y * 128 + wm * 64 + i * 16 + g;
#pragma unroll
        for (int j = 0; j < 4; j++) {
            int lcol = wn * 32 + j * 8 + t * 2;
            ll col = (ll)blockIdx.x * 128 + lcol;
            float b0 = bp ? bp[lcol] : 0.f;
            float b1 = bp ? bp[lcol + 1] : 0.f;
            float2 v0, v1;
            v0.x = alpha * acc[i][j][0] + b0;
            v0.y = alpha * acc[i][j][1] + b1;
            v1.x = alpha * acc[i][j][2] + b0;
            v1.y = alpha * acc[i][j][3] + b1;
            *reinterpret_cast<float2*>(Cp + r0 * ldc + col)       = v0;
            *reinterpret_cast<float2*>(Cp + (r0 + 8) * ldc + col) = v1;
        }
    }
}

// ---------------------------------------------------------------------------
// tf32 mma.sync GEMM (single pass, fp32 operands straight from gmem):
// C[i,j] = alpha * sum_k A[i,k]*B[j,k] + bias[j]
// CTA 128x128, 8 warps, K-chunk 16 (rows padded to 20 floats: conflict-free).
// ---------------------------------------------------------------------------
__global__ void __launch_bounds__(256, 2) k_tf32_gemm(
    const float* __restrict__ A, ll lda, ll sAb, ll sAh,
    const float* __restrict__ Bm, ll ldb, ll sBb, ll sBh,
    const float* __restrict__ bias, ll sbb, float alpha,
    float* __restrict__ C, ll ldc, ll sCb, ll sCh, int K)
{
    __shared__ float sA[2][128][20];
    __shared__ float sB[2][128][20];

    const int tid = threadIdx.x, lane = tid & 31, wid = tid >> 5;
    const int wm = wid & 1, wn = wid >> 1;
    const int z = blockIdx.z, b = z >> 3, h = z & 7;
    const float* Ab = A + b * sAb + h * sAh + (ll)blockIdx.y * 128 * lda;
    const float* Bb = Bm + b * sBb + h * sBh + (ll)blockIdx.x * 128 * ldb;

    float acc[4][4][4];
#pragma unroll
    for (int i = 0; i < 4; i++)
#pragma unroll
        for (int j = 0; j < 4; j++)
#pragma unroll
            for (int r = 0; r < 4; r++) acc[i][j][r] = 0.f;

    const int g = lane >> 2, t = lane & 3;
    const int nch = K >> 4;

#define LOAD_STAGE_T(st, kt)                                                   \
    do {                                                                       \
        _Pragma("unroll")                                                      \
        for (int it = 0; it < 2; it++) {                                       \
            int idx = tid + it * 256;                                          \
            int r = idx >> 2, cc = (idx & 3) * 4;                              \
            cp16(smem_u32(&sA[st][r][cc]), Ab + (ll)r * lda + (kt) + cc);      \
            cp16(smem_u32(&sB[st][r][cc]), Bb + (ll)r * ldb + (kt) + cc);      \
        }                                                                      \
        CP_COMMIT();                                                           \
    } while (0)

    LOAD_STAGE_T(0, 0);

    for (int c = 0; c < nch; c++) {
        if (c + 1 < nch) {
            LOAD_STAGE_T((c + 1) & 1, (c + 1) * 16);
            CP_WAIT(1);
        } else {
            CP_WAIT(0);
        }
        __syncthreads();

        const int st = c & 1;
#pragma unroll
        for (int k0 = 0; k0 < 16; k0 += 8) {
            uint32_t af[4][4], bfr[4][2];
#pragma unroll
            for (int i = 0; i < 4; i++) {
                int r = wm * 64 + i * 16 + g;
                af[i][0] = to_tf32(sA[st][r][k0 + t]);
                af[i][1] = to_tf32(sA[st][r + 8][k0 + t]);
                af[i][2] = to_tf32(sA[st][r][k0 + t + 4]);
                af[i][3] = to_tf32(sA[st][r + 8][k0 + t + 4]);
            }
#pragma unroll
            for (int j = 0; j < 4; j++) {
                int n = wn * 32 + j * 8 + g;
                bfr[j][0] = to_tf32(sB[st][n][k0 + t]);
                bfr[j][1] = to_tf32(sB[st][n][k0 + t + 4]);
            }
#pragma unroll
            for (int i = 0; i < 4; i++)
#pragma unroll
                for (int j = 0; j < 4; j++)
                    mma1688(acc[i][j], af[i], bfr[j][0], bfr[j][1]);
        }
        __syncthreads();
    }
#undef LOAD_STAGE_T

    float* Cp = C + b * sCb + h * sCh;
    const float* bp = bias ? bias + b * sbb + (ll)blockIdx.x * 128 : nullptr;
#pragma unroll
    for (int i = 0; i < 4; i++) {
        ll r0 = (ll)blockIdx.y * 128 + wm * 64 + i * 16 + g;
#pragma unroll
        for (int j = 0; j < 4; j++) {
            int lcol = wn * 32 + j * 8 + t * 2;
            ll col = (ll)blockIdx.x * 128 + lcol;
            float b0 = bp ? bp[lcol] : 0.f;
            float b1 = bp ? bp[lcol + 1] : 0.f;
            float2 v0, v1;
            v0.x = alpha * acc[i][j][0] + b0;
            v0.y = alpha * acc[i][j][1] + b1;
            v1.x = alpha * acc[i][j][2] + b0;
            v1.y = alpha * acc[i][j][3] + b1;
            *reinterpret_cast<float2*>(Cp + r0 * ldc + col)       = v0;
            *reinterpret_cast<float2*>(Cp + (r0 + 8) * ldc + col) = v1;
        }
    }
}

// ---------------------------------------------------------------------------
// Fused RoPE + split-bf16 conversion.
// Reads g_Q (fp32) and K half of g_KV; writes g_Qb (A-mode) and g_Kb (B-mode).
// One block per (b,s), 128 threads (half-dim index).
// ---------------------------------------------------------------------------
__global__ void k_rope_fused(const int* __restrict__ pos_ids) {
    int bs = blockIdx.x;
    int i  = threadIdx.x;
    double invf = exp(-(double)i * (9.210340371976182736 / 128.0));
    double sv, cv;
    sincos((double)pos_ids[bs] * invf, &sv, &cv);
    float c = (float)cv, s = (float)sv;

    // K head
    const float* kv = g_KV + (size_t)bs * 512;
    float x1 = kv[i], x2 = kv[128 + i];
    float k1 = c * x1 - s * x2;
    float k2 = s * x1 + c * x2;
    bf16* kb = g_Kb + (size_t)bs * 768;
    bf16 kh1 = __float2bfloat16(k1), kh2 = __float2bfloat16(k2);
    kb[i]       = kh1;  kb[128 + i] = kh2;
    kb[256 + i] = __float2bfloat16(k1 - __bfloat162float(kh1));
    kb[384 + i] = __float2bfloat16(k2 - __bfloat162float(kh2));
    kb[512 + i] = kh1;  kb[640 + i] = kh2;

    // Q heads
    const float* q = g_Q + (size_t)bs * (HH * DD);
#pragma unroll
    for (int h = 0; h < HH; h++) {
        float y1 = q[h * DD + i], y2 = q[h * DD + 128 + i];
        float q1 = c * y1 - s * y2;
        float q2 = s * y1 + c * y2;
        bf16* qb = g_Qb + ((size_t)bs * HH + h) * 768;
        bf16 qh1 = __float2bfloat16(q1), qh2 = __float2bfloat16(q2);
        qb[i]       = qh1;  qb[128 + i] = qh2;
        qb[256 + i] = qh1;  qb[384 + i] = qh2;
        qb[512 + i] = __float2bfloat16(q1 - __bfloat162float(qh1));
        qb[640 + i] = __float2bfloat16(q2 - __bfloat162float(qh2));
    }
}

// ---------------------------------------------------------------------------
// Transpose V: g_KV (b, m, [256 + d]) -> g_Vt (b, d, m), fp32.
// ---------------------------------------------------------------------------
__global__ void k_transpose_v() {
    __shared__ float tile[32][33];
    int b  = blockIdx.z;
    int m0 = blockIdx.y * 32;
    int d0 = blockIdx.x * 32;
    int x = threadIdx.x, y = threadIdx.y;
#pragma unroll
    for (int j = 0; j < 32; j += 8)
        tile[y + j][x] = g_KV[((size_t)(b * SSQ + m0 + y + j)) * 512 + 256 + d0 + x];
    __syncthreads();
#pragma unroll
    for (int j = 0; j < 32; j += 8)
        g_Vt[(size_t)b * DD * SSQ + (size_t)(d0 + y + j) * SSQ + m0 + x] = tile[x][y + j];
}

// ---------------------------------------------------------------------------
// Row softmax over 2048, in place (fp32).
// ---------------------------------------------------------------------------
__global__ void k_softmax(float* __restrict__ attn) {
    size_t row = blockIdx.x;
    float* p = attn + row * SSQ;
    int tid = threadIdx.x;

    float v[8];
    float m = -1e30f;
#pragma unroll
    for (int i = 0; i < 8; i++) { v[i] = p[i * 256 + tid]; m = fmaxf(m, v[i]); }

    __shared__ float red[256];
    red[tid] = m; __syncthreads();
    for (int s = 128; s > 0; s >>= 1) {
        if (tid < s) red[tid] = fmaxf(red[tid], red[tid + s]);
        __syncthreads();
    }
    m = red[0]; __syncthreads();

    float sum = 0.f;
#pragma unroll
    for (int i = 0; i < 8; i++) { v[i] = __expf(v[i] - m); sum += v[i]; }
    red[tid] = sum; __syncthreads();
    for (int s = 128; s > 0; s >>= 1) {
        if (tid < s) red[tid] += red[tid + s];
        __syncthreads();
    }
    float inv = 1.f / red[0];
#pragma unroll
    for (int i = 0; i < 8; i++) p[i * 256 + tid] = v[i] * inv;
}

// ---------------------------------------------------------------------------
// Launch
// ---------------------------------------------------------------------------
extern "C" void kernel_launch(void* const* d_in, const int* in_sizes, int n_in,
                              void* d_out, int out_size) {
    const float* hs   = (const float*)d_in[0];
    const float* mask = (const float*)d_in[1];
    const int*   pos  = (const int*)d_in[2];
    const float* Wq   = (const float*)d_in[3];
    const float* bq   = (const float*)d_in[4];
    const float* Wk   = (const float*)d_in[5];
    const float* bk   = (const float*)d_in[6];
    const float* Wv   = (const float*)d_in[7];
    const float* bv   = (const float*)d_in[8];
    const float* Wo   = (const float*)d_in[9];
    const float* bo   = (const float*)d_in[10];
    float* out = (float*)d_out;

    const size_t out_elems  = (size_t)BB * SSQ * HIDD;
    const size_t attn_elems = (size_t)BB * HH * SSQ * SSQ;

    float* attn;
    if ((size_t)out_size >= out_elems + attn_elems) {
        attn = out + out_elems;
    } else {
        void* p = nullptr;
        cudaGetSymbolAddress(&p, g_Scores);
        attn = (float*)p;
    }

    // Resolve scratch symbol addresses (host side, capture-safe lookups)
    bf16 *hsb, *Wqb, *Wkvb, *Qb, *Kb;
    float *bkv, *Qf, *KVf, *Vtf, *Ctxf;
    { void* p;
      cudaGetSymbolAddress(&p, g_hsb);  hsb  = (bf16*)p;
      cudaGetSymbolAddress(&p, g_Wqb);  Wqb  = (bf16*)p;
      cudaGetSymbolAddress(&p, g_Wkvb); Wkvb = (bf16*)p;
      cudaGetSymbolAddress(&p, g_bkv);  bkv  = (float*)p;
      cudaGetSymbolAddress(&p, g_Q);    Qf   = (float*)p;
      cudaGetSymbolAddress(&p, g_KV);   KVf  = (float*)p;
      cudaGetSymbolAddress(&p, g_Qb);   Qb   = (bf16*)p;
      cudaGetSymbolAddress(&p, g_Kb);   Kb   = (bf16*)p;
      cudaGetSymbolAddress(&p, g_Vt);   Vtf  = (float*)p;
      cudaGetSymbolAddress(&p, g_Ctx);  Ctxf = (float*)p;
    }

    const int T = 256;
    auto blocks = [](ll n2) { return (unsigned)((n2 + 255) / 256); };

    // 1) Split-convert hs + projection weights (bf16 3-term path)
    ll n2_hs = (ll)BB * SSQ * HIDD / 2;
    k_cvt_split<<<blocks(n2_hs), T>>>(hs, hsb, 11, 1, n2_hs);
    ll n2_wq = (ll)HH * DD * HIDD / 2;
    k_cvt_split<<<blocks(n2_wq), T>>>(Wq, Wqb, 11, 0, n2_wq);
    ll n2_wk = (ll)DD * HIDD / 2;
    k_cvt_split<<<blocks(n2_wk), T>>>(Wk, Wkvb, 11, 0, n2_wk);
    k_cvt_split<<<blocks(n2_wk), T>>>(Wv, Wkvb + (size_t)DD * 3 * HIDD, 11, 0, n2_wk);
    k_merge_bias<<<1, 2 * DD>>>(bk, bv);

    // 2) Q projection + merged KV projection (bf16 3-term, K' = 6144)
    k_mma_gemm<<<dim3(16, 32, 1), T>>>(hsb, 6144, 0, 0, Wqb, 6144, 0, 0,
                                       bq, 0, 1.f, Qf, 2048, 0, 0, 6144);
    k_mma_gemm<<<dim3(4, 32, 1), T>>>(hsb, 6144, 0, 0, Wkvb, 6144, 0, 0,
                                      bkv, 0, 1.f, KVf, 512, 0, 0, 6144);

    // 3) Fused RoPE + split conversion; V transpose (fp32)
    k_rope_fused<<<BB * SSQ, 128>>>(pos);
    k_transpose_v<<<dim3(DD / 32, SSQ / 32, BB), dim3(32, 8)>>>();

    // 4) scores[b,h] = Q K^T / 16 + mask  (bf16 3-term, K' = 768)
    k_mma_gemm<<<dim3(16, 16, BB * HH), T>>>(
        Qb, (ll)HH * 3 * DD, (ll)SSQ * HH * 3 * DD, 3 * DD,
        Kb, 3 * DD, (ll)SSQ * 3 * DD, 0,
        mask, SSQ, 0.0625f,
        attn, SSQ, (ll)HH * SSQ * SSQ, (ll)SSQ * SSQ, 3 * DD);

    // 5) softmax (fp32, in place)
    k_softmax<<<BB * HH * SSQ, 256>>>(attn);

    // 6) ctx = attn @ V  (tf32 single pass, fp32 operands, K = 2048)
    k_tf32_gemm<<<dim3(2, 16, BB * HH), T>>>(
        attn, SSQ, (ll)HH * SSQ * SSQ, (ll)SSQ * SSQ,
        Vtf, SSQ, (ll)DD * SSQ, 0,
        nullptr, 0, 1.f,
        Ctxf, HH * DD, (ll)SSQ * HH * DD, DD, SSQ);

    // 7) out = ctx @ Wo^T + bo  (tf32 single pass, K = 2048)
    k_tf32_gemm<<<dim3(16, 32, 1), T>>>(
        Ctxf, 2048, 0, 0, Wo, 2048, 0, 0,
        bo, 0, 1.f, out, 2048, 0, 0, 2048);
}